// round 3
// baseline (speedup 1.0000x reference)
#include <cuda_runtime.h>
#include <cstdint>

// Problem constants (fixed by the dataset)
#define BDIM   16384   // batch
#define FDIM   256     // features
#define BOND   16
#define NFREQ  4
#define DIN0   (1 + 2*NFREQ)   // 9
#define ROWS   4               // rows per thread (mid + level0)

// ---------------- scratch buffers (no cudaMalloc allowed) ----------------
__device__ float g_xT[FDIM * BDIM];                  // 16 MB  : x transposed (F, B)
__device__ float g_bufA[128 * BDIM * BOND];          // 128 MB : ping
__device__ float g_bufB[64  * BDIM * BOND];          // 64 MB  : pong

// ---------------- f32x2 packed-FMA helpers (Blackwell) -------------------
__device__ __forceinline__ unsigned long long ffma2(unsigned long long a,
                                                    unsigned long long b,
                                                    unsigned long long c) {
    unsigned long long d;
    asm("fma.rn.f32x2 %0, %1, %2, %3;" : "=l"(d) : "l"(a), "l"(b), "l"(c));
    return d;
}
__device__ __forceinline__ unsigned long long pack2(float x, float y) {
    unsigned long long r;
    asm("mov.b64 %0, {%1, %2};" : "=l"(r) : "f"(x), "f"(y));
    return r;
}
__device__ __forceinline__ float2 unpack2(unsigned long long v) {
    float2 f;
    asm("mov.b64 {%0, %1}, %2;" : "=f"(f.x), "=f"(f.y) : "l"(v));
    return f;
}

// ---------------- x transpose: (B,F) -> (F,B), coalesced both sides ------
__global__ __launch_bounds__(256) void tt_transpose(const float* __restrict__ x,
                                                    float* __restrict__ xT) {
    __shared__ float tile[32][33];
    const int c0 = blockIdx.x * 32;   // feature tile
    const int r0 = blockIdx.y * 32;   // batch tile
    #pragma unroll
    for (int k = 0; k < 4; ++k) {
        int r = r0 + threadIdx.y + 8 * k;
        tile[threadIdx.y + 8 * k][threadIdx.x] = x[(size_t)r * FDIM + c0 + threadIdx.x];
    }
    __syncthreads();
    #pragma unroll
    for (int k = 0; k < 4; ++k) {
        int c = c0 + threadIdx.y + 8 * k;
        xT[(size_t)c * BDIM + r0 + threadIdx.x] = tile[threadIdx.x][threadIdx.y + 8 * k];
    }
}

// ---------------- Fourier feature builder --------------------------------
__device__ __forceinline__ void fourier9(float xv, float fmin, float* f) {
    float a = xv * fmin;
    float s1, c1; sincosf(a, &s1, &c1);
    float s2 = s1 * c1 + c1 * s1, c2 = c1 * c1 - s1 * s1;
    float s3 = s2 * c1 + c2 * s1, c3 = c2 * c1 - s2 * s1;
    float s4 = s3 * c1 + c3 * s1, c4 = c3 * c1 - s3 * s1;
    f[0] = 1.f; f[1] = s1; f[2] = s2; f[3] = s3; f[4] = s4;
    f[5] = c1;  f[6] = c2; f[7] = c3; f[8] = c4;
}

// ---------------- level 0: Fourier feats + 9x9x16 bilinear, 4 rows/thread -
// grid: (128 pairs, B/512), block 128. out layout (128, B, 16).
__global__ __launch_bounds__(128) void tt_level0(const float* __restrict__ xT,
                                                 const float* __restrict__ fminp,
                                                 const float* __restrict__ W0,
                                                 float* __restrict__ out) {
    __shared__ __align__(16) float sW[DIN0 * DIN0 * BOND];   // 1296 floats
    const int p   = blockIdx.x;
    const int tid = threadIdx.x;

    {
        const float4* wg  = reinterpret_cast<const float4*>(W0 + (size_t)p * (DIN0 * DIN0 * BOND));
        float4*       ws4 = reinterpret_cast<float4*>(sW);
        for (int k = tid; k < (DIN0 * DIN0 * BOND) / 4; k += 128) ws4[k] = wg[k];
    }
    __syncthreads();

    const int   bb   = blockIdx.y * (128 * ROWS) + tid;
    const float fmin = *fminp;

    float l[ROWS][DIN0];
    float r[ROWS][DIN0];         // dynamically indexed by j -> local mem (cheap)
    #pragma unroll
    for (int row = 0; row < ROWS; ++row) {
        int b = bb + 128 * row;
        fourier9(xT[(size_t)(2 * p)     * BDIM + b], fmin, l[row]);
        fourier9(xT[(size_t)(2 * p + 1) * BDIM + b], fmin, r[row]);
    }

    unsigned long long acc[ROWS][8];
    #pragma unroll
    for (int row = 0; row < ROWS; ++row)
        #pragma unroll
        for (int k = 0; k < 8; ++k) acc[row][k] = 0ull;

    #pragma unroll 1
    for (int j = 0; j < DIN0; ++j) {
        float rv[ROWS];
        #pragma unroll
        for (int row = 0; row < ROWS; ++row) rv[row] = r[row][j];
        #pragma unroll
        for (int i = 0; i < DIN0; ++i) {
            const ulonglong2* wv = reinterpret_cast<const ulonglong2*>(sW + (i * DIN0 + j) * BOND);
            ulonglong2 w0 = wv[0], w1 = wv[1], w2 = wv[2], w3 = wv[3];
            #pragma unroll
            for (int row = 0; row < ROWS; ++row) {
                float x = l[row][i] * rv[row];
                unsigned long long px = pack2(x, x);
                acc[row][0] = ffma2(px, w0.x, acc[row][0]);
                acc[row][1] = ffma2(px, w0.y, acc[row][1]);
                acc[row][2] = ffma2(px, w1.x, acc[row][2]);
                acc[row][3] = ffma2(px, w1.y, acc[row][3]);
                acc[row][4] = ffma2(px, w2.x, acc[row][4]);
                acc[row][5] = ffma2(px, w2.y, acc[row][5]);
                acc[row][6] = ffma2(px, w3.x, acc[row][6]);
                acc[row][7] = ffma2(px, w3.y, acc[row][7]);
            }
        }
    }

    #pragma unroll
    for (int row = 0; row < ROWS; ++row) {
        int b = bb + 128 * row;
        float4* op = reinterpret_cast<float4*>(out + ((size_t)p * BDIM + b) * BOND);
        #pragma unroll
        for (int k = 0; k < 4; ++k) {
            float2 u = unpack2(acc[row][2 * k]), v = unpack2(acc[row][2 * k + 1]);
            op[k] = make_float4(u.x, u.y, v.x, v.y);
        }
    }
}

// ---------------- levels 1..6: 16x16x16 bilinear, 4 rows/thread -----------
// grid: (P pairs, B/512), block 128. in (2P, B, 16) -> out (P, B, 16).
__global__ __launch_bounds__(128) void tt_level_mid(const float* __restrict__ in,
                                                    const float* __restrict__ W,
                                                    float* __restrict__ out) {
    __shared__ __align__(16) float sW[BOND * BOND * BOND];   // 4096 floats = 16 KB
    const int p   = blockIdx.x;
    const int tid = threadIdx.x;

    {
        const float4* wg  = reinterpret_cast<const float4*>(W + (size_t)p * (BOND * BOND * BOND));
        float4*       ws4 = reinterpret_cast<float4*>(sW);
        #pragma unroll
        for (int k = 0; k < 8; ++k) ws4[tid + 128 * k] = wg[tid + 128 * k];
    }
    __syncthreads();

    const int bb = blockIdx.y * (128 * ROWS) + tid;

    float l[ROWS][BOND];          // constant-indexed (i fully unrolled) -> registers
    float r[ROWS][BOND];          // dynamically indexed by j -> local mem (L1-cached)
    #pragma unroll
    for (int row = 0; row < ROWS; ++row) {
        int b = bb + 128 * row;
        const float4* lp = reinterpret_cast<const float4*>(in + ((size_t)(2 * p)     * BDIM + b) * BOND);
        const float4* rp = reinterpret_cast<const float4*>(in + ((size_t)(2 * p + 1) * BDIM + b) * BOND);
        #pragma unroll
        for (int k = 0; k < 4; ++k) {
            float4 v;
            v = lp[k]; l[row][4*k] = v.x; l[row][4*k+1] = v.y; l[row][4*k+2] = v.z; l[row][4*k+3] = v.w;
            v = rp[k]; r[row][4*k] = v.x; r[row][4*k+1] = v.y; r[row][4*k+2] = v.z; r[row][4*k+3] = v.w;
        }
    }

    unsigned long long acc[ROWS][8];
    #pragma unroll
    for (int row = 0; row < ROWS; ++row)
        #pragma unroll
        for (int k = 0; k < 8; ++k) acc[row][k] = 0ull;

    #pragma unroll 1
    for (int j = 0; j < BOND; ++j) {
        float rv[ROWS];
        #pragma unroll
        for (int row = 0; row < ROWS; ++row) rv[row] = r[row][j];
        #pragma unroll
        for (int i = 0; i < BOND; ++i) {
            const ulonglong2* wv = reinterpret_cast<const ulonglong2*>(sW + (i * BOND + j) * BOND);
            ulonglong2 w0 = wv[0], w1 = wv[1], w2 = wv[2], w3 = wv[3];
            #pragma unroll
            for (int row = 0; row < ROWS; ++row) {
                float x = l[row][i] * rv[row];
                unsigned long long px = pack2(x, x);
                acc[row][0] = ffma2(px, w0.x, acc[row][0]);
                acc[row][1] = ffma2(px, w0.y, acc[row][1]);
                acc[row][2] = ffma2(px, w1.x, acc[row][2]);
                acc[row][3] = ffma2(px, w1.y, acc[row][3]);
                acc[row][4] = ffma2(px, w2.x, acc[row][4]);
                acc[row][5] = ffma2(px, w2.y, acc[row][5]);
                acc[row][6] = ffma2(px, w3.x, acc[row][6]);
                acc[row][7] = ffma2(px, w3.y, acc[row][7]);
            }
        }
    }

    #pragma unroll
    for (int row = 0; row < ROWS; ++row) {
        int b = bb + 128 * row;
        float4* op = reinterpret_cast<float4*>(out + ((size_t)p * BDIM + b) * BOND);
        #pragma unroll
        for (int k = 0; k < 4; ++k) {
            float2 u = unpack2(acc[row][2 * k]), v = unpack2(acc[row][2 * k + 1]);
            op[k] = make_float4(u.x, u.y, v.x, v.y);
        }
    }
}

// ---------------- level 7: 16x16 -> scalar --------------------------------
__global__ __launch_bounds__(256) void tt_level7(const float* __restrict__ in,
                                                 const float* __restrict__ W,
                                                 float* __restrict__ out) {
    __shared__ float sW[BOND * BOND];
    const int tid = threadIdx.x;
    if (tid < BOND * BOND) sW[tid] = W[tid];
    __syncthreads();

    const int b = blockIdx.x * 256 + tid;
    float l[BOND], r[BOND];
    {
        const float4* lp = reinterpret_cast<const float4*>(in + ((size_t)0 * BDIM + b) * BOND);
        const float4* rp = reinterpret_cast<const float4*>(in + ((size_t)1 * BDIM + b) * BOND);
        #pragma unroll
        for (int k = 0; k < 4; ++k) {
            float4 v = lp[k]; l[4 * k] = v.x; l[4 * k + 1] = v.y; l[4 * k + 2] = v.z; l[4 * k + 3] = v.w;
            float4 u = rp[k]; r[4 * k] = u.x; r[4 * k + 1] = u.y; r[4 * k + 2] = u.z; r[4 * k + 3] = u.w;
        }
    }
    float acc = 0.f;
    #pragma unroll
    for (int i = 0; i < BOND; ++i) {
        float t = 0.f;
        #pragma unroll
        for (int j = 0; j < BOND; ++j) t = fmaf(sW[i * BOND + j], r[j], t);
        acc = fmaf(l[i], t, acc);
    }
    out[b] = acc;
}

// --------------------------------- launch ---------------------------------
extern "C" void kernel_launch(void* const* d_in, const int* in_sizes, int n_in,
                              void* d_out, int out_size) {
    const float* x    = (const float*)d_in[0];
    const float* fmin = (const float*)d_in[1];
    const float* W[8];
    for (int i = 0; i < 8; ++i) W[i] = (const float*)d_in[2 + i];

    float *xT, *bufA, *bufB;
    cudaGetSymbolAddress((void**)&xT,   g_xT);
    cudaGetSymbolAddress((void**)&bufA, g_bufA);
    cudaGetSymbolAddress((void**)&bufB, g_bufB);

    const int BT = BDIM / (128 * ROWS);   // 32 row-tiles of 512 rows

    tt_transpose<<<dim3(FDIM / 32, BDIM / 32), dim3(32, 8)>>>(x, xT);
    tt_level0  <<<dim3(128, BT), 128>>>(xT, fmin, W[0], bufA);
    tt_level_mid<<<dim3(64, BT), 128>>>(bufA, W[1], bufB);
    tt_level_mid<<<dim3(32, BT), 128>>>(bufB, W[2], bufA);
    tt_level_mid<<<dim3(16, BT), 128>>>(bufA, W[3], bufB);
    tt_level_mid<<<dim3( 8, BT), 128>>>(bufB, W[4], bufA);
    tt_level_mid<<<dim3( 4, BT), 128>>>(bufA, W[5], bufB);
    tt_level_mid<<<dim3( 2, BT), 128>>>(bufB, W[6], bufA);
    tt_level7  <<<BDIM / 256, 256>>>(bufA, W[7], (float*)d_out);
}

// round 4
// speedup vs baseline: 1.0958x; 1.0958x over previous
#include <cuda_runtime.h>
#include <cstdint>

// Problem constants (fixed by the dataset)
#define BDIM   16384   // batch
#define FDIM   256     // features
#define BOND   16
#define NFREQ  4
#define DIN0   (1 + 2*NFREQ)   // 9

// ---------------- scratch buffers (no cudaMalloc allowed) ----------------
__device__ float g_xT[FDIM * BDIM];                  // 16 MB  : x transposed (F, B)
__device__ float g_bufA[128 * BDIM * BOND];          // 128 MB : ping
__device__ float g_bufB[64  * BDIM * BOND];          // 64 MB  : pong

// ---------------- f32x2 packed-FMA helpers (Blackwell) -------------------
__device__ __forceinline__ unsigned long long ffma2(unsigned long long a,
                                                    unsigned long long b,
                                                    unsigned long long c) {
    unsigned long long d;
    asm("fma.rn.f32x2 %0, %1, %2, %3;" : "=l"(d) : "l"(a), "l"(b), "l"(c));
    return d;
}
__device__ __forceinline__ unsigned long long pack2(float x, float y) {
    unsigned long long r;
    asm("mov.b64 %0, {%1, %2};" : "=l"(r) : "f"(x), "f"(y));
    return r;
}
__device__ __forceinline__ float2 unpack2(unsigned long long v) {
    float2 f;
    asm("mov.b64 {%0, %1}, %2;" : "=f"(f.x), "=f"(f.y) : "l"(v));
    return f;
}

// ---------------- x transpose: (B,F) -> (F,B), coalesced both sides ------
__global__ __launch_bounds__(256) void tt_transpose(const float* __restrict__ x,
                                                    float* __restrict__ xT) {
    __shared__ float tile[32][33];
    const int c0 = blockIdx.x * 32;   // feature tile
    const int r0 = blockIdx.y * 32;   // batch tile
    #pragma unroll
    for (int k = 0; k < 4; ++k) {
        int r = r0 + threadIdx.y + 8 * k;
        tile[threadIdx.y + 8 * k][threadIdx.x] = x[(size_t)r * FDIM + c0 + threadIdx.x];
    }
    __syncthreads();
    #pragma unroll
    for (int k = 0; k < 4; ++k) {
        int c = c0 + threadIdx.y + 8 * k;
        xT[(size_t)c * BDIM + r0 + threadIdx.x] = tile[threadIdx.x][threadIdx.y + 8 * k];
    }
}

// ---------------- Fourier feature builder --------------------------------
__device__ __forceinline__ void fourier9(float xv, float fmin, float* f) {
    float a = xv * fmin;
    float s1, c1; sincosf(a, &s1, &c1);
    float s2 = s1 * c1 + c1 * s1, c2 = c1 * c1 - s1 * s1;
    float s3 = s2 * c1 + c2 * s1, c3 = c2 * c1 - s2 * s1;
    float s4 = s3 * c1 + c3 * s1, c4 = c3 * c1 - s3 * s1;
    f[0] = 1.f; f[1] = s1; f[2] = s2; f[3] = s3; f[4] = s4;
    f[5] = c1;  f[6] = c2; f[7] = c3; f[8] = c4;
}

// ---------------- level 0: Fourier feats + 9x9x16 bilinear ---------------
// grid: (128 pairs, B/(128*R)), block 128. out layout (128, B, 16).
// l in registers (constant-indexed), r in SMEM (dynamic j index, conflict-free).
template<int R>
__global__ __launch_bounds__(128, 3) void tt_level0(const float* __restrict__ xT,
                                                    const float* __restrict__ fminp,
                                                    const float* __restrict__ W0,
                                                    float* __restrict__ out) {
    __shared__ __align__(16) float sW[DIN0 * DIN0 * BOND];   // 5184 B
    __shared__ float sR[DIN0][128 * R];
    const int p   = blockIdx.x;
    const int tid = threadIdx.x;

    {
        const float4* wg  = reinterpret_cast<const float4*>(W0 + (size_t)p * (DIN0 * DIN0 * BOND));
        float4*       ws4 = reinterpret_cast<float4*>(sW);
        for (int k = tid; k < (DIN0 * DIN0 * BOND) / 4; k += 128) ws4[k] = wg[k];
    }

    const int   bb   = blockIdx.y * (128 * R) + tid;
    const float fmin = *fminp;

    float l[R][DIN0];
    #pragma unroll
    for (int row = 0; row < R; ++row) {
        int b = bb + 128 * row;
        fourier9(xT[(size_t)(2 * p) * BDIM + b], fmin, l[row]);
        float rr[DIN0];
        fourier9(xT[(size_t)(2 * p + 1) * BDIM + b], fmin, rr);
        #pragma unroll
        for (int j = 0; j < DIN0; ++j) sR[j][row * 128 + tid] = rr[j];
    }
    __syncthreads();

    unsigned long long acc[R][8];
    #pragma unroll
    for (int row = 0; row < R; ++row)
        #pragma unroll
        for (int k = 0; k < 8; ++k) acc[row][k] = 0ull;

    #pragma unroll 3
    for (int j = 0; j < DIN0; ++j) {
        float rv[R];
        #pragma unroll
        for (int row = 0; row < R; ++row) rv[row] = sR[j][row * 128 + tid];
        #pragma unroll
        for (int i = 0; i < DIN0; ++i) {
            const ulonglong2* wv = reinterpret_cast<const ulonglong2*>(sW + (i * DIN0 + j) * BOND);
            ulonglong2 w0 = wv[0], w1 = wv[1], w2 = wv[2], w3 = wv[3];
            #pragma unroll
            for (int row = 0; row < R; ++row) {
                float x = l[row][i] * rv[row];
                unsigned long long px = pack2(x, x);
                acc[row][0] = ffma2(px, w0.x, acc[row][0]);
                acc[row][1] = ffma2(px, w0.y, acc[row][1]);
                acc[row][2] = ffma2(px, w1.x, acc[row][2]);
                acc[row][3] = ffma2(px, w1.y, acc[row][3]);
                acc[row][4] = ffma2(px, w2.x, acc[row][4]);
                acc[row][5] = ffma2(px, w2.y, acc[row][5]);
                acc[row][6] = ffma2(px, w3.x, acc[row][6]);
                acc[row][7] = ffma2(px, w3.y, acc[row][7]);
            }
        }
    }

    #pragma unroll
    for (int row = 0; row < R; ++row) {
        int b = bb + 128 * row;
        float4* op = reinterpret_cast<float4*>(out + ((size_t)p * BDIM + b) * BOND);
        #pragma unroll
        for (int k = 0; k < 4; ++k) {
            float2 u = unpack2(acc[row][2 * k]), v = unpack2(acc[row][2 * k + 1]);
            op[k] = make_float4(u.x, u.y, v.x, v.y);
        }
    }
}

// ---------------- levels 1..6: 16x16x16 bilinear ---------------------------
// grid: (P pairs, B/(128*R)), block 128. in (2P, B, 16) -> out (P, B, 16).
template<int R>
__global__ __launch_bounds__(128, 3) void tt_level_mid(const float* __restrict__ in,
                                                       const float* __restrict__ W,
                                                       float* __restrict__ out) {
    __shared__ __align__(16) float sW[BOND * BOND * BOND];   // 16 KB
    __shared__ float sR[BOND][128 * R];                       // up to 32 KB
    const int p   = blockIdx.x;
    const int tid = threadIdx.x;

    {
        const float4* wg  = reinterpret_cast<const float4*>(W + (size_t)p * (BOND * BOND * BOND));
        float4*       ws4 = reinterpret_cast<float4*>(sW);
        #pragma unroll
        for (int k = 0; k < 8; ++k) ws4[tid + 128 * k] = wg[tid + 128 * k];
    }

    const int bb = blockIdx.y * (128 * R) + tid;

    float l[R][BOND];                 // registers (i fully unrolled)
    #pragma unroll
    for (int row = 0; row < R; ++row) {
        int b = bb + 128 * row;
        const float4* lp = reinterpret_cast<const float4*>(in + ((size_t)(2 * p)     * BDIM + b) * BOND);
        const float4* rp = reinterpret_cast<const float4*>(in + ((size_t)(2 * p + 1) * BDIM + b) * BOND);
        #pragma unroll
        for (int k = 0; k < 4; ++k) {
            float4 v = lp[k];
            l[row][4*k] = v.x; l[row][4*k+1] = v.y; l[row][4*k+2] = v.z; l[row][4*k+3] = v.w;
            float4 u = rp[k];
            sR[4*k  ][row * 128 + tid] = u.x;
            sR[4*k+1][row * 128 + tid] = u.y;
            sR[4*k+2][row * 128 + tid] = u.z;
            sR[4*k+3][row * 128 + tid] = u.w;
        }
    }
    __syncthreads();

    unsigned long long acc[R][8];
    #pragma unroll
    for (int row = 0; row < R; ++row)
        #pragma unroll
        for (int k = 0; k < 8; ++k) acc[row][k] = 0ull;

    #pragma unroll 2
    for (int j = 0; j < BOND; ++j) {
        float rv[R];
        #pragma unroll
        for (int row = 0; row < R; ++row) rv[row] = sR[j][row * 128 + tid];
        #pragma unroll
        for (int i = 0; i < BOND; ++i) {
            const ulonglong2* wv = reinterpret_cast<const ulonglong2*>(sW + (i * BOND + j) * BOND);
            ulonglong2 w0 = wv[0], w1 = wv[1], w2 = wv[2], w3 = wv[3];
            #pragma unroll
            for (int row = 0; row < R; ++row) {
                float x = l[row][i] * rv[row];
                unsigned long long px = pack2(x, x);
                acc[row][0] = ffma2(px, w0.x, acc[row][0]);
                acc[row][1] = ffma2(px, w0.y, acc[row][1]);
                acc[row][2] = ffma2(px, w1.x, acc[row][2]);
                acc[row][3] = ffma2(px, w1.y, acc[row][3]);
                acc[row][4] = ffma2(px, w2.x, acc[row][4]);
                acc[row][5] = ffma2(px, w2.y, acc[row][5]);
                acc[row][6] = ffma2(px, w3.x, acc[row][6]);
                acc[row][7] = ffma2(px, w3.y, acc[row][7]);
            }
        }
    }

    #pragma unroll
    for (int row = 0; row < R; ++row) {
        int b = bb + 128 * row;
        float4* op = reinterpret_cast<float4*>(out + ((size_t)p * BDIM + b) * BOND);
        #pragma unroll
        for (int k = 0; k < 4; ++k) {
            float2 u = unpack2(acc[row][2 * k]), v = unpack2(acc[row][2 * k + 1]);
            op[k] = make_float4(u.x, u.y, v.x, v.y);
        }
    }
}

// ---------------- level 7: 16x16 -> scalar --------------------------------
__global__ __launch_bounds__(256) void tt_level7(const float* __restrict__ in,
                                                 const float* __restrict__ W,
                                                 float* __restrict__ out) {
    __shared__ float sW[BOND * BOND];
    const int tid = threadIdx.x;
    if (tid < BOND * BOND) sW[tid] = W[tid];
    __syncthreads();

    const int b = blockIdx.x * 256 + tid;
    float l[BOND], r[BOND];
    {
        const float4* lp = reinterpret_cast<const float4*>(in + ((size_t)0 * BDIM + b) * BOND);
        const float4* rp = reinterpret_cast<const float4*>(in + ((size_t)1 * BDIM + b) * BOND);
        #pragma unroll
        for (int k = 0; k < 4; ++k) {
            float4 v = lp[k]; l[4 * k] = v.x; l[4 * k + 1] = v.y; l[4 * k + 2] = v.z; l[4 * k + 3] = v.w;
            float4 u = rp[k]; r[4 * k] = u.x; r[4 * k + 1] = u.y; r[4 * k + 2] = u.z; r[4 * k + 3] = u.w;
        }
    }
    float acc = 0.f;
    #pragma unroll
    for (int i = 0; i < BOND; ++i) {
        float t = 0.f;
        #pragma unroll
        for (int j = 0; j < BOND; ++j) t = fmaf(sW[i * BOND + j], r[j], t);
        acc = fmaf(l[i], t, acc);
    }
    out[b] = acc;
}

// --------------------------------- launch ---------------------------------
extern "C" void kernel_launch(void* const* d_in, const int* in_sizes, int n_in,
                              void* d_out, int out_size) {
    const float* x    = (const float*)d_in[0];
    const float* fmin = (const float*)d_in[1];
    const float* W[8];
    for (int i = 0; i < 8; ++i) W[i] = (const float*)d_in[2 + i];

    float *xT, *bufA, *bufB;
    cudaGetSymbolAddress((void**)&xT,   g_xT);
    cudaGetSymbolAddress((void**)&bufA, g_bufA);
    cudaGetSymbolAddress((void**)&bufB, g_bufB);

    // Row-tiles: big levels use R=4 (W amortization), tiny-pair tail levels use
    // smaller R to keep >= 256 CTAs in flight on 148 SMs.
    const int BT4 = BDIM / (128 * 4);   // 32
    const int BT2 = BDIM / (128 * 2);   // 64
    const int BT1 = BDIM / (128 * 1);   // 128

    tt_transpose<<<dim3(FDIM / 32, BDIM / 32), dim3(32, 8)>>>(x, xT);
    tt_level0<4>  <<<dim3(128, BT4), 128>>>(xT, fmin, W[0], bufA);
    tt_level_mid<4><<<dim3(64, BT4), 128>>>(bufA, W[1], bufB);
    tt_level_mid<4><<<dim3(32, BT4), 128>>>(bufB, W[2], bufA);
    tt_level_mid<4><<<dim3(16, BT4), 128>>>(bufA, W[3], bufB);
    tt_level_mid<4><<<dim3( 8, BT4), 128>>>(bufB, W[4], bufA);
    tt_level_mid<2><<<dim3( 4, BT2), 128>>>(bufA, W[5], bufB);
    tt_level_mid<1><<<dim3( 2, BT1), 128>>>(bufB, W[6], bufA);
    tt_level7  <<<BDIM / 256, 256>>>(bufA, W[7], (float*)d_out);
}

// round 5
// speedup vs baseline: 1.1338x; 1.0347x over previous
#include <cuda_runtime.h>
#include <cstdint>

#define BDIM   16384
#define FDIM   256
#define BOND   16
#define NFREQ  4
#define DIN0   (1 + 2*NFREQ)   // 9

__device__ float g_xT[FDIM * BDIM];
__device__ float g_bufA[128 * BDIM * BOND];
__device__ float g_bufB[64  * BDIM * BOND];

__device__ __forceinline__ unsigned long long ffma2(unsigned long long a,
                                                    unsigned long long b,
                                                    unsigned long long c) {
    unsigned long long d;
    asm("fma.rn.f32x2 %0, %1, %2, %3;" : "=l"(d) : "l"(a), "l"(b), "l"(c));
    return d;
}
__device__ __forceinline__ unsigned long long pack2(float x, float y) {
    unsigned long long r;
    asm("mov.b64 %0, {%1, %2};" : "=l"(r) : "f"(x), "f"(y));
    return r;
}
__device__ __forceinline__ float2 unpack2(unsigned long long v) {
    float2 f;
    asm("mov.b64 {%0, %1}, %2;" : "=f"(f.x), "=f"(f.y) : "l"(v));
    return f;
}

// ---------------- x transpose: (B,F) -> (F,B) ----------------------------
__global__ __launch_bounds__(256) void tt_transpose(const float* __restrict__ x,
                                                    float* __restrict__ xT) {
    __shared__ float tile[32][33];
    const int c0 = blockIdx.x * 32;
    const int r0 = blockIdx.y * 32;
    #pragma unroll
    for (int k = 0; k < 4; ++k) {
        int r = r0 + threadIdx.y + 8 * k;
        tile[threadIdx.y + 8 * k][threadIdx.x] = x[(size_t)r * FDIM + c0 + threadIdx.x];
    }
    __syncthreads();
    #pragma unroll
    for (int k = 0; k < 4; ++k) {
        int c = c0 + threadIdx.y + 8 * k;
        xT[(size_t)c * BDIM + r0 + threadIdx.x] = tile[threadIdx.x][threadIdx.y + 8 * k];
    }
}

// ---------------- Fourier feature builder (fast path; arg in [0,1)) ------
__device__ __forceinline__ void fourier9(float xv, float fmin, float* f) {
    float a = xv * fmin;
    float s1, c1;
    __sincosf(a, &s1, &c1);
    float s2 = s1 * c1 + c1 * s1, c2 = c1 * c1 - s1 * s1;
    float s3 = s2 * c1 + c2 * s1, c3 = c2 * c1 - s2 * s1;
    float s4 = s3 * c1 + c3 * s1, c4 = c3 * c1 - s3 * s1;
    f[0] = 1.f; f[1] = s1; f[2] = s2; f[3] = s3; f[4] = s4;
    f[5] = c1;  f[6] = c2; f[7] = c3; f[8] = c4;
}

// ---------------- level 0: Fourier feats + 9x9x16 bilinear ---------------
template<int R>
__global__ __launch_bounds__(128, 3) void tt_level0(const float* __restrict__ xT,
                                                    const float* __restrict__ fminp,
                                                    const float* __restrict__ W0,
                                                    float* __restrict__ out) {
    __shared__ __align__(16) float sW[DIN0 * DIN0 * BOND];
    __shared__ float sR[DIN0][128 * R];
    const int p   = blockIdx.x;
    const int tid = threadIdx.x;

    {
        const float4* wg  = reinterpret_cast<const float4*>(W0 + (size_t)p * (DIN0 * DIN0 * BOND));
        float4*       ws4 = reinterpret_cast<float4*>(sW);
        for (int k = tid; k < (DIN0 * DIN0 * BOND) / 4; k += 128) ws4[k] = wg[k];
    }

    const int   bb   = blockIdx.y * (128 * R) + tid;
    const float fmin = *fminp;

    float l[R][DIN0];
    #pragma unroll
    for (int row = 0; row < R; ++row) {
        int b = bb + 128 * row;
        fourier9(xT[(size_t)(2 * p) * BDIM + b], fmin, l[row]);
        float rr[DIN0];
        fourier9(xT[(size_t)(2 * p + 1) * BDIM + b], fmin, rr);
        #pragma unroll
        for (int j = 0; j < DIN0; ++j) sR[j][row * 128 + tid] = rr[j];
    }
    __syncthreads();

    unsigned long long acc[R][8];
    #pragma unroll
    for (int row = 0; row < R; ++row)
        #pragma unroll
        for (int k = 0; k < 8; ++k) acc[row][k] = 0ull;

    #pragma unroll 3
    for (int j = 0; j < DIN0; ++j) {
        float rv[R];
        #pragma unroll
        for (int row = 0; row < R; ++row) rv[row] = sR[j][row * 128 + tid];
        #pragma unroll
        for (int i = 0; i < DIN0; ++i) {
            const ulonglong2* wv = reinterpret_cast<const ulonglong2*>(sW + (i * DIN0 + j) * BOND);
            ulonglong2 w0 = wv[0], w1 = wv[1], w2 = wv[2], w3 = wv[3];
            #pragma unroll
            for (int row = 0; row < R; ++row) {
                float x = l[row][i] * rv[row];
                unsigned long long px = pack2(x, x);
                acc[row][0] = ffma2(px, w0.x, acc[row][0]);
                acc[row][1] = ffma2(px, w0.y, acc[row][1]);
                acc[row][2] = ffma2(px, w1.x, acc[row][2]);
                acc[row][3] = ffma2(px, w1.y, acc[row][3]);
                acc[row][4] = ffma2(px, w2.x, acc[row][4]);
                acc[row][5] = ffma2(px, w2.y, acc[row][5]);
                acc[row][6] = ffma2(px, w3.x, acc[row][6]);
                acc[row][7] = ffma2(px, w3.y, acc[row][7]);
            }
        }
    }

    #pragma unroll
    for (int row = 0; row < R; ++row) {
        int b = bb + 128 * row;
        float4* op = reinterpret_cast<float4*>(out + ((size_t)p * BDIM + b) * BOND);
        #pragma unroll
        for (int k = 0; k < 4; ++k) {
            float2 u = unpack2(acc[row][2 * k]), v = unpack2(acc[row][2 * k + 1]);
            op[k] = make_float4(u.x, u.y, v.x, v.y);
        }
    }
}

// ---------------- levels 1..6: 16x16x16 bilinear ---------------------------
template<int R>
__global__ __launch_bounds__(128, 3) void tt_level_mid(const float* __restrict__ in,
                                                       const float* __restrict__ W,
                                                       float* __restrict__ out) {
    __shared__ __align__(16) float sW[BOND * BOND * BOND];
    __shared__ float sR[BOND][128 * R];
    const int p   = blockIdx.x;
    const int tid = threadIdx.x;

    {
        const float4* wg  = reinterpret_cast<const float4*>(W + (size_t)p * (BOND * BOND * BOND));
        float4*       ws4 = reinterpret_cast<float4*>(sW);
        #pragma unroll
        for (int k = 0; k < 8; ++k) ws4[tid + 128 * k] = wg[tid + 128 * k];
    }

    const int bb = blockIdx.y * (128 * R) + tid;

    float l[R][BOND];
    #pragma unroll
    for (int row = 0; row < R; ++row) {
        int b = bb + 128 * row;
        const float4* lp = reinterpret_cast<const float4*>(in + ((size_t)(2 * p)     * BDIM + b) * BOND);
        const float4* rp = reinterpret_cast<const float4*>(in + ((size_t)(2 * p + 1) * BDIM + b) * BOND);
        #pragma unroll
        for (int k = 0; k < 4; ++k) {
            float4 v = lp[k];
            l[row][4*k] = v.x; l[row][4*k+1] = v.y; l[row][4*k+2] = v.z; l[row][4*k+3] = v.w;
            float4 u = rp[k];
            sR[4*k  ][row * 128 + tid] = u.x;
            sR[4*k+1][row * 128 + tid] = u.y;
            sR[4*k+2][row * 128 + tid] = u.z;
            sR[4*k+3][row * 128 + tid] = u.w;
        }
    }
    __syncthreads();

    unsigned long long acc[R][8];
    #pragma unroll
    for (int row = 0; row < R; ++row)
        #pragma unroll
        for (int k = 0; k < 8; ++k) acc[row][k] = 0ull;

    #pragma unroll 4
    for (int j = 0; j < BOND; ++j) {
        float rv[R];
        #pragma unroll
        for (int row = 0; row < R; ++row) rv[row] = sR[j][row * 128 + tid];
        #pragma unroll
        for (int i = 0; i < BOND; ++i) {
            const ulonglong2* wv = reinterpret_cast<const ulonglong2*>(sW + (i * BOND + j) * BOND);
            ulonglong2 w0 = wv[0], w1 = wv[1], w2 = wv[2], w3 = wv[3];
            #pragma unroll
            for (int row = 0; row < R; ++row) {
                float x = l[row][i] * rv[row];
                unsigned long long px = pack2(x, x);
                acc[row][0] = ffma2(px, w0.x, acc[row][0]);
                acc[row][1] = ffma2(px, w0.y, acc[row][1]);
                acc[row][2] = ffma2(px, w1.x, acc[row][2]);
                acc[row][3] = ffma2(px, w1.y, acc[row][3]);
                acc[row][4] = ffma2(px, w2.x, acc[row][4]);
                acc[row][5] = ffma2(px, w2.y, acc[row][5]);
                acc[row][6] = ffma2(px, w3.x, acc[row][6]);
                acc[row][7] = ffma2(px, w3.y, acc[row][7]);
            }
        }
    }

    #pragma unroll
    for (int row = 0; row < R; ++row) {
        int b = bb + 128 * row;
        float4* op = reinterpret_cast<float4*>(out + ((size_t)p * BDIM + b) * BOND);
        #pragma unroll
        for (int k = 0; k < 4; ++k) {
            float2 u = unpack2(acc[row][2 * k]), v = unpack2(acc[row][2 * k + 1]);
            op[k] = make_float4(u.x, u.y, v.x, v.y);
        }
    }
}

// ---------------- level 7: 16x16 -> scalar --------------------------------
__global__ __launch_bounds__(128) void tt_level7(const float* __restrict__ in,
                                                 const float* __restrict__ W,
                                                 float* __restrict__ out) {
    __shared__ float sW[BOND * BOND];
    const int tid = threadIdx.x;
    if (tid < BOND * BOND / 2) {
        reinterpret_cast<float2*>(sW)[tid] = reinterpret_cast<const float2*>(W)[tid];
    }
    __syncthreads();

    const int b = blockIdx.x * 128 + tid;
    float l[BOND], r[BOND];
    {
        const float4* lp = reinterpret_cast<const float4*>(in + ((size_t)0 * BDIM + b) * BOND);
        const float4* rp = reinterpret_cast<const float4*>(in + ((size_t)1 * BDIM + b) * BOND);
        #pragma unroll
        for (int k = 0; k < 4; ++k) {
            float4 v = lp[k]; l[4 * k] = v.x; l[4 * k + 1] = v.y; l[4 * k + 2] = v.z; l[4 * k + 3] = v.w;
            float4 u = rp[k]; r[4 * k] = u.x; r[4 * k + 1] = u.y; r[4 * k + 2] = u.z; r[4 * k + 3] = u.w;
        }
    }
    float acc = 0.f;
    #pragma unroll
    for (int i = 0; i < BOND; ++i) {
        float t = 0.f;
        #pragma unroll
        for (int j = 0; j < BOND; ++j) t = fmaf(sW[i * BOND + j], r[j], t);
        acc = fmaf(l[i], t, acc);
    }
    out[b] = acc;
}

// --------------------------------- launch ---------------------------------
extern "C" void kernel_launch(void* const* d_in, const int* in_sizes, int n_in,
                              void* d_out, int out_size) {
    const float* x    = (const float*)d_in[0];
    const float* fmin = (const float*)d_in[1];
    const float* W[8];
    for (int i = 0; i < 8; ++i) W[i] = (const float*)d_in[2 + i];

    float *xT, *bufA, *bufB;
    cudaGetSymbolAddress((void**)&xT,   g_xT);
    cudaGetSymbolAddress((void**)&bufA, g_bufA);
    cudaGetSymbolAddress((void**)&bufB, g_bufB);

    const int BT4 = BDIM / (128 * 4);   // 32
    const int BT2 = BDIM / (128 * 2);   // 64
    const int BT1 = BDIM / (128 * 1);   // 128

    tt_transpose<<<dim3(FDIM / 32, BDIM / 32), dim3(32, 8)>>>(x, xT);
    tt_level0<4>   <<<dim3(128, BT4), 128>>>(xT, fmin, W[0], bufA);
    tt_level_mid<4><<<dim3(64, BT4), 128>>>(bufA, W[1], bufB);   // 2048 CTAs
    tt_level_mid<4><<<dim3(32, BT4), 128>>>(bufB, W[2], bufA);   // 1024
    tt_level_mid<4><<<dim3(16, BT4), 128>>>(bufA, W[3], bufB);   //  512
    tt_level_mid<2><<<dim3( 8, BT2), 128>>>(bufB, W[4], bufA);   //  512
    tt_level_mid<2><<<dim3( 4, BT2), 128>>>(bufA, W[5], bufB);   //  256
    tt_level_mid<1><<<dim3( 2, BT1), 128>>>(bufB, W[6], bufA);   //  256
    tt_level7      <<<BDIM / 128, 128>>>(bufA, W[7], (float*)d_out);
}